// round 1
// baseline (speedup 1.0000x reference)
#include <cuda_runtime.h>
#include <cuda_bf16.h>

// Problem constants
#define BB 8
#define CC 256
#define HH 64
#define WW 64
#define EE 32
#define KK 8192
#define NN 32768      // B*H*W
#define HWW 4096      // H*W

#define DECAY 0.99f
#define ONE_MINUS_DECAY 0.01f
#define EPSI 1e-5f
#define BETA 0.25f

// Output layout (flattened tuple, f32)
#define OFF_ZQ   0
#define OFF_IDX  1048576
#define OFF_QL   1081344
#define OFF_EMB  1081345
#define OFF_CS   1343489
#define OFF_W    1351681

// Scratch (device globals — no allocation allowed)
__device__ float g_z[NN * EE];     // 4 MB: z_flat [N][E]
__device__ float g_en[KK * EE];    // 1 MB: normalized embedding
__device__ float g_counts[KK];
__device__ float g_dw[KK * EE];    // 1 MB
__device__ int   g_bidx[NN];
__device__ float g_qsum;
__device__ float g_nsum;

// ---- packed f32x2 helpers ----
__device__ __forceinline__ void fma2(unsigned long long& acc, unsigned long long a, unsigned long long b) {
    asm("fma.rn.f32x2 %0, %1, %2, %0;" : "+l"(acc) : "l"(a), "l"(b));
}
__device__ __forceinline__ float2 unpack2(unsigned long long v) {
    float2 r;
    asm("mov.b64 {%0, %1}, %2;" : "=f"(r.x), "=f"(r.y) : "l"(v));
    return r;
}

// ---------------- zero scratch ----------------
__global__ void zero_kernel() {
    int i = blockIdx.x * blockDim.x + threadIdx.x;
    int stride = gridDim.x * blockDim.x;
    for (int j = i; j < KK * EE; j += stride) g_dw[j] = 0.0f;
    for (int j = i; j < KK; j += stride) g_counts[j] = 0.0f;
    if (i == 0) { g_qsum = 0.0f; g_nsum = 0.0f; }
}

// ---------------- 1x1 conv: z[n][e] = sum_c x[b,c,p]*Wq[e,c] + bq[e] ----------------
// 16 pixels per block, 256 threads. Shared: Wq (32KB) + x tile (16KB) = 48KB.
__global__ __launch_bounds__(256) void proj_kernel(
    const float* __restrict__ x, const float* __restrict__ Wq, const float* __restrict__ bq)
{
    __shared__ float sW[EE * CC];   // [e][c] 32KB
    __shared__ float sx[CC * 16];   // [c][pix] 16KB
    const int t = threadIdx.x;
    const int n0 = blockIdx.x * 16;
    const int b = n0 >> 12;
    const int p0 = n0 & (HWW - 1);

    for (int i = t; i < EE * CC; i += 256) sW[i] = Wq[i];
    const float* xb = x + (size_t)b * CC * HWW + p0;
    #pragma unroll
    for (int j = 0; j < 16; j++) {
        int idx = j * 256 + t;
        int c = idx >> 4, pix = idx & 15;
        sx[idx] = xb[c * HWW + pix];
    }
    __syncthreads();

    const int pix = t & 15;
    const int e0 = (t >> 4) << 1;   // 2 e-values per thread
    float a0 = 0.0f, a1 = 0.0f;
    #pragma unroll 8
    for (int c = 0; c < CC; c++) {
        float xv = sx[c * 16 + pix];
        a0 = fmaf(xv, sW[(e0 + 0) * CC + c], a0);
        a1 = fmaf(xv, sW[(e0 + 1) * CC + c], a1);
    }
    float* zr = g_z + (size_t)(n0 + pix) * EE + e0;
    zr[0] = a0 + bq[e0];
    zr[1] = a1 + bq[e0 + 1];
}

// ---------------- normalize embedding rows ----------------
__global__ __launch_bounds__(256) void enorm_kernel(const float* __restrict__ emb) {
    int k = blockIdx.x * 8 + (threadIdx.x >> 5);
    int e = threadIdx.x & 31;
    float v = emb[k * EE + e];
    float s = v * v;
    #pragma unroll
    for (int o = 16; o; o >>= 1) s += __shfl_xor_sync(0xFFFFFFFFu, s, o);
    float nrm = fmaxf(sqrtf(s), 1e-12f);
    g_en[k * EE + e] = v / nrm;
}

// ---------------- argmax over K of dot(z, en_k) ----------------
// 1 pixel per thread, 256 threads/block, 128 blocks. en streamed in 256-code chunks (32KB).
__global__ __launch_bounds__(256, 2) void argmax_kernel() {
    __shared__ float4 sE[256 * 8];   // 256 codes x 32 floats = 32KB
    const int t = threadIdx.x;
    const int n = blockIdx.x * 256 + t;

    // Load z row into 16 packed f32x2 registers
    unsigned long long zp[16];
    const ulonglong2* zr = reinterpret_cast<const ulonglong2*>(g_z + (size_t)n * EE);
    #pragma unroll
    for (int i = 0; i < 8; i++) { ulonglong2 v = zr[i]; zp[2 * i] = v.x; zp[2 * i + 1] = v.y; }

    float best = -3.0e38f;
    int bidx = 0;

    for (int kc = 0; kc < KK; kc += 256) {
        __syncthreads();
        const float4* src = reinterpret_cast<const float4*>(g_en + (size_t)kc * EE);
        #pragma unroll
        for (int i = 0; i < 8; i++) sE[i * 256 + t] = src[i * 256 + t];
        __syncthreads();

        #pragma unroll 2
        for (int kk = 0; kk < 256; kk++) {
            const ulonglong2* er = reinterpret_cast<const ulonglong2*>(&sE[kk * 8]);
            unsigned long long a0 = 0ull, a1 = 0ull;   // (0.0f, 0.0f)
            #pragma unroll
            for (int j = 0; j < 4; j++) {
                ulonglong2 e01 = er[2 * j];
                ulonglong2 e23 = er[2 * j + 1];
                fma2(a0, zp[4 * j + 0], e01.x);
                fma2(a1, zp[4 * j + 1], e01.y);
                fma2(a0, zp[4 * j + 2], e23.x);
                fma2(a1, zp[4 * j + 3], e23.y);
            }
            float2 f0 = unpack2(a0);
            float2 f1 = unpack2(a1);
            float s = (f0.x + f0.y) + (f1.x + f1.y);
            if (s > best) { best = s; bidx = kc + kk; }   // strict > keeps first max (jnp.argmax)
        }
    }
    g_bidx[n] = bidx;
}

// ---------------- gather z_q, qloss partial, EMA scatter, indices out ----------------
__global__ __launch_bounds__(256) void gather_kernel(const float* __restrict__ emb, float* __restrict__ out) {
    const int t = threadIdx.x;
    const int n = blockIdx.x * 256 + t;
    const int idx = g_bidx[n];
    const int b = n >> 12, p = n & (HWW - 1);

    float ev[EE];
    const float4* er = reinterpret_cast<const float4*>(emb + (size_t)idx * EE);
    #pragma unroll
    for (int i = 0; i < 8; i++) {
        float4 v = er[i];
        ev[4 * i] = v.x; ev[4 * i + 1] = v.y; ev[4 * i + 2] = v.z; ev[4 * i + 3] = v.w;
    }

    const float* zrow = g_z + (size_t)n * EE;
    float* dwr = g_dw + (size_t)idx * EE;
    float sq = 0.0f;
    #pragma unroll
    for (int e = 0; e < EE; e++) {
        float zv = zrow[e];
        float d = ev[e] - zv;
        sq = fmaf(d, d, sq);
        atomicAdd(&dwr[e], zv);
    }
    atomicAdd(&g_counts[idx], 1.0f);

    // z_q_st (numerically == z_q = embedding[idx]) in [B,E,H,W] layout; coalesced across p
    float* ob = out + OFF_ZQ + (size_t)b * EE * HWW + p;
    #pragma unroll
    for (int e = 0; e < EE; e++) ob[(size_t)e * HWW] = ev[e];

    out[OFF_IDX + n] = (float)idx;

    __shared__ float red[256];
    red[t] = sq;
    __syncthreads();
    #pragma unroll
    for (int s = 128; s; s >>= 1) {
        if (t < s) red[t] += red[t + s];
        __syncthreads();
    }
    if (t == 0) atomicAdd(&g_qsum, red[0]);
}

// ---------------- EMA stage 1: new_cs + total n ----------------
__global__ __launch_bounds__(256) void ema1_kernel(const float* __restrict__ ema_cs, float* __restrict__ out) {
    const int t = threadIdx.x;
    const int k = blockIdx.x * 256 + t;
    float c = DECAY * ema_cs[k] + ONE_MINUS_DECAY * g_counts[k];
    out[OFF_CS + k] = c;
    __shared__ float red[256];
    red[t] = c;
    __syncthreads();
    #pragma unroll
    for (int s = 128; s; s >>= 1) {
        if (t < s) red[t] += red[t + s];
        __syncthreads();
    }
    if (t == 0) atomicAdd(&g_nsum, red[0]);
}

// ---------------- EMA stage 2: new_w, new_embedding, qloss ----------------
__global__ __launch_bounds__(256) void ema2_kernel(const float* __restrict__ ema_w, float* __restrict__ out) {
    const int i = blockIdx.x * 256 + threadIdx.x;   // over K*E
    const int k = i >> 5;
    float w = DECAY * ema_w[i] + ONE_MINUS_DECAY * g_dw[i];
    out[OFF_W + i] = w;
    float nt = g_nsum;
    float c = out[OFF_CS + k];
    float cs = (c + EPSI) / (nt + (float)KK * EPSI) * nt;
    out[OFF_EMB + i] = w / cs;
    if (i == 0) out[OFF_QL] = BETA * g_qsum / (float)(NN * EE);
}

extern "C" void kernel_launch(void* const* d_in, const int* in_sizes, int n_in,
                              void* d_out, int out_size) {
    const float* x   = (const float*)d_in[0];
    const float* Wq  = (const float*)d_in[1];
    const float* bq  = (const float*)d_in[2];
    const float* emb = (const float*)d_in[3];
    const float* ecs = (const float*)d_in[4];
    const float* ew  = (const float*)d_in[5];
    float* out = (float*)d_out;

    zero_kernel<<<264, 512>>>();
    proj_kernel<<<NN / 16, 256>>>(x, Wq, bq);
    enorm_kernel<<<KK / 8, 256>>>(emb);
    argmax_kernel<<<NN / 256, 256>>>();
    gather_kernel<<<NN / 256, 256>>>(emb, out);
    ema1_kernel<<<KK / 256, 256>>>(ecs, out);
    ema2_kernel<<<(KK * EE) / 256, 256>>>(ew, out);
}

// round 2
// speedup vs baseline: 1.4398x; 1.4398x over previous
#include <cuda_runtime.h>
#include <cuda_bf16.h>

// Problem constants
#define BB 8
#define CC 256
#define HH 64
#define WW 64
#define EE 32
#define KK 8192
#define NN 32768      // B*H*W
#define HWW 4096      // H*W

#define NSPLIT 4
#define KCHUNK 2048   // KK / NSPLIT

#define DECAY 0.99f
#define ONE_MINUS_DECAY 0.01f
#define EPSI 1e-5f
#define BETA 0.25f

// Output layout (flattened tuple, f32)
#define OFF_ZQ   0
#define OFF_IDX  1048576
#define OFF_QL   1081344
#define OFF_EMB  1081345
#define OFF_CS   1343489
#define OFF_W    1351681

// Scratch (device globals — no allocation allowed)
__device__ float g_z[NN * EE];         // 4 MB: z_flat [N][E]
__device__ float g_en[KK * EE];        // 1 MB: normalized embedding
__device__ float g_counts[KK];
__device__ float g_dw[KK * EE];        // 1 MB
__device__ float g_pbest[NSPLIT * NN]; // split-K partial max values
__device__ int   g_pidx[NSPLIT * NN];  // split-K partial argmax
__device__ float g_qsum;
__device__ float g_nsum;

// ---- packed f32x2 helpers ----
__device__ __forceinline__ void fma2(unsigned long long& acc, unsigned long long a, unsigned long long b) {
    asm("fma.rn.f32x2 %0, %1, %2, %0;" : "+l"(acc) : "l"(a), "l"(b));
}
__device__ __forceinline__ float2 unpack2(unsigned long long v) {
    float2 r;
    asm("mov.b64 {%0, %1}, %2;" : "=f"(r.x), "=f"(r.y) : "l"(v));
    return r;
}

// ---------------- zero scratch ----------------
__global__ void zero_kernel() {
    int i = blockIdx.x * blockDim.x + threadIdx.x;
    int stride = gridDim.x * blockDim.x;
    for (int j = i; j < KK * EE; j += stride) g_dw[j] = 0.0f;
    for (int j = i; j < KK; j += stride) g_counts[j] = 0.0f;
    if (i == 0) { g_qsum = 0.0f; g_nsum = 0.0f; }
}

// ---------------- 1x1 conv: z[n][e] = sum_c x[b,c,p]*Wq[e,c] + bq[e] ----------------
__global__ __launch_bounds__(256) void proj_kernel(
    const float* __restrict__ x, const float* __restrict__ Wq, const float* __restrict__ bq)
{
    __shared__ float sW[EE * CC];   // [e][c] 32KB
    __shared__ float sx[CC * 16];   // [c][pix] 16KB
    const int t = threadIdx.x;
    const int n0 = blockIdx.x * 16;
    const int b = n0 >> 12;
    const int p0 = n0 & (HWW - 1);

    for (int i = t; i < EE * CC; i += 256) sW[i] = Wq[i];
    const float* xb = x + (size_t)b * CC * HWW + p0;
    #pragma unroll
    for (int j = 0; j < 16; j++) {
        int idx = j * 256 + t;
        int c = idx >> 4, pix = idx & 15;
        sx[idx] = xb[c * HWW + pix];
    }
    __syncthreads();

    const int pix = t & 15;
    const int e0 = (t >> 4) << 1;   // 2 e-values per thread
    float a0 = 0.0f, a1 = 0.0f;
    #pragma unroll 8
    for (int c = 0; c < CC; c++) {
        float xv = sx[c * 16 + pix];
        a0 = fmaf(xv, sW[(e0 + 0) * CC + c], a0);
        a1 = fmaf(xv, sW[(e0 + 1) * CC + c], a1);
    }
    float* zr = g_z + (size_t)(n0 + pix) * EE + e0;
    zr[0] = a0 + bq[e0];
    zr[1] = a1 + bq[e0 + 1];
}

// ---------------- normalize embedding rows ----------------
__global__ __launch_bounds__(256) void enorm_kernel(const float* __restrict__ emb) {
    int k = blockIdx.x * 8 + (threadIdx.x >> 5);
    int e = threadIdx.x & 31;
    float v = emb[k * EE + e];
    float s = v * v;
    #pragma unroll
    for (int o = 16; o; o >>= 1) s += __shfl_xor_sync(0xFFFFFFFFu, s, o);
    float nrm = fmaxf(sqrtf(s), 1e-12f);
    g_en[k * EE + e] = v / nrm;
}

// ---------------- argmax over K-split of dot(z, en_k), 2 pixels/thread ----------------
// grid = 64 pixel-tiles (512 px each) * NSPLIT. Each thread: pixels n0+t, n0+t+256.
// en streamed through 32KB shared chunks (256 codes); 8 LDS.128/code serve 2 pixels.
__global__ __launch_bounds__(256, 2) void argmax_kernel() {
    __shared__ ulonglong2 sE[256 * 8];   // 256 codes x 32 floats = 32KB
    const int t = threadIdx.x;
    const int tile = blockIdx.x & 63;
    const int split = blockIdx.x >> 6;
    const int nA = tile * 512 + t;
    const int nB = nA + 256;
    const int kbase = split * KCHUNK;

    // Load both z rows into packed f32x2 registers (natural adjacent-e pairs)
    unsigned long long zA[16], zB[16];
    {
        const ulonglong2* ra = reinterpret_cast<const ulonglong2*>(g_z + (size_t)nA * EE);
        const ulonglong2* rb = reinterpret_cast<const ulonglong2*>(g_z + (size_t)nB * EE);
        #pragma unroll
        for (int i = 0; i < 8; i++) {
            ulonglong2 va = ra[i]; zA[2 * i] = va.x; zA[2 * i + 1] = va.y;
            ulonglong2 vb = rb[i]; zB[2 * i] = vb.x; zB[2 * i + 1] = vb.y;
        }
    }

    float bestA = -3.0e38f, bestB = -3.0e38f;
    int idxA = 0, idxB = 0;

    for (int kc = 0; kc < KCHUNK; kc += 256) {
        __syncthreads();
        const ulonglong2* src = reinterpret_cast<const ulonglong2*>(g_en + (size_t)(kbase + kc) * EE);
        #pragma unroll
        for (int i = 0; i < 8; i++) sE[i * 256 + t] = src[i * 256 + t];
        __syncthreads();

        #pragma unroll 2
        for (int kk = 0; kk < 256; kk++) {
            const ulonglong2* er = &sE[kk * 8];
            unsigned long long a = 0ull, b = 0ull;
            #pragma unroll
            for (int j = 0; j < 8; j++) {
                ulonglong2 e2 = er[j];
                fma2(a, zA[2 * j],     e2.x);
                fma2(a, zA[2 * j + 1], e2.y);
                fma2(b, zB[2 * j],     e2.x);
                fma2(b, zB[2 * j + 1], e2.y);
            }
            float2 fa = unpack2(a);
            float2 fb = unpack2(b);
            float sA = fa.x + fa.y;
            float sB = fb.x + fb.y;
            int k = kbase + kc + kk;
            bool pA = sA > bestA;       // strict > keeps first max
            bool pB = sB > bestB;
            bestA = pA ? sA : bestA;  idxA = pA ? k : idxA;
            bestB = pB ? sB : bestB;  idxB = pB ? k : idxB;
        }
    }
    g_pbest[split * NN + nA] = bestA;  g_pidx[split * NN + nA] = idxA;
    g_pbest[split * NN + nB] = bestB;  g_pidx[split * NN + nB] = idxB;
}

// ---------------- merge splits + gather z_q, qloss partial, EMA scatter ----------------
__global__ __launch_bounds__(256) void gather_kernel(const float* __restrict__ emb, float* __restrict__ out) {
    const int t = threadIdx.x;
    const int n = blockIdx.x * 256 + t;

    // merge split-K partials (ascending split order, strict > => first-max semantics)
    float best = g_pbest[n];
    int idx = g_pidx[n];
    #pragma unroll
    for (int s = 1; s < NSPLIT; s++) {
        float v = g_pbest[s * NN + n];
        int id = g_pidx[s * NN + n];
        bool p = v > best;
        best = p ? v : best;
        idx = p ? id : idx;
    }

    const int b = n >> 12, p = n & (HWW - 1);

    float ev[EE];
    const float4* er = reinterpret_cast<const float4*>(emb + (size_t)idx * EE);
    #pragma unroll
    for (int i = 0; i < 8; i++) {
        float4 v = er[i];
        ev[4 * i] = v.x; ev[4 * i + 1] = v.y; ev[4 * i + 2] = v.z; ev[4 * i + 3] = v.w;
    }

    const float* zrow = g_z + (size_t)n * EE;
    float* dwr = g_dw + (size_t)idx * EE;
    float sq = 0.0f;
    #pragma unroll
    for (int e = 0; e < EE; e++) {
        float zv = zrow[e];
        float d = ev[e] - zv;
        sq = fmaf(d, d, sq);
        atomicAdd(&dwr[e], zv);
    }
    atomicAdd(&g_counts[idx], 1.0f);

    // z_q_st (numerically == z_q = embedding[idx]) in [B,E,H,W] layout; coalesced across p
    float* ob = out + OFF_ZQ + (size_t)b * EE * HWW + p;
    #pragma unroll
    for (int e = 0; e < EE; e++) ob[(size_t)e * HWW] = ev[e];

    out[OFF_IDX + n] = (float)idx;

    __shared__ float red[256];
    red[t] = sq;
    __syncthreads();
    #pragma unroll
    for (int s = 128; s; s >>= 1) {
        if (t < s) red[t] += red[t + s];
        __syncthreads();
    }
    if (t == 0) atomicAdd(&g_qsum, red[0]);
}

// ---------------- EMA stage 1: new_cs + total n ----------------
__global__ __launch_bounds__(256) void ema1_kernel(const float* __restrict__ ema_cs, float* __restrict__ out) {
    const int t = threadIdx.x;
    const int k = blockIdx.x * 256 + t;
    float c = DECAY * ema_cs[k] + ONE_MINUS_DECAY * g_counts[k];
    out[OFF_CS + k] = c;
    __shared__ float red[256];
    red[t] = c;
    __syncthreads();
    #pragma unroll
    for (int s = 128; s; s >>= 1) {
        if (t < s) red[t] += red[t + s];
        __syncthreads();
    }
    if (t == 0) atomicAdd(&g_nsum, red[0]);
}

// ---------------- EMA stage 2: new_w, new_embedding, qloss ----------------
__global__ __launch_bounds__(256) void ema2_kernel(const float* __restrict__ ema_w, float* __restrict__ out) {
    const int i = blockIdx.x * 256 + threadIdx.x;   // over K*E
    const int k = i >> 5;
    float w = DECAY * ema_w[i] + ONE_MINUS_DECAY * g_dw[i];
    out[OFF_W + i] = w;
    float nt = g_nsum;
    float c = out[OFF_CS + k];
    float cs = (c + EPSI) / (nt + (float)KK * EPSI) * nt;
    out[OFF_EMB + i] = w / cs;
    if (i == 0) out[OFF_QL] = BETA * g_qsum / (float)(NN * EE);
}

extern "C" void kernel_launch(void* const* d_in, const int* in_sizes, int n_in,
                              void* d_out, int out_size) {
    const float* x   = (const float*)d_in[0];
    const float* Wq  = (const float*)d_in[1];
    const float* bq  = (const float*)d_in[2];
    const float* emb = (const float*)d_in[3];
    const float* ecs = (const float*)d_in[4];
    const float* ew  = (const float*)d_in[5];
    float* out = (float*)d_out;

    zero_kernel<<<264, 512>>>();
    proj_kernel<<<NN / 16, 256>>>(x, Wq, bq);
    enorm_kernel<<<KK / 8, 256>>>(emb);
    argmax_kernel<<<64 * NSPLIT, 256>>>();
    gather_kernel<<<NN / 256, 256>>>(emb, out);
    ema1_kernel<<<KK / 256, 256>>>(ecs, out);
    ema2_kernel<<<(KK * EE) / 256, 256>>>(ew, out);
}